// round 14
// baseline (speedup 1.0000x reference)
#include <cuda_runtime.h>
#include <cuda_fp16.h>
#include <mma.h>
#include <cstdint>

using namespace nvcuda;

#define BSZ   2
#define SEQL  2048
#define DIM   4096
#define NH    32
#define NKV   8
#define HD    128
#define NTOK  (BSZ * SEQL)        // 4096
#define KVDIM (NKV * HD)          // 1024
#define NQKV  (DIM + 2 * KVDIM)   // 6144

// ---------------- scratch (device globals: allocation-guard safe) ----------
__device__ __half g_xh   [(size_t)NTOK * DIM];     // fp16 x
__device__ __half g_wqkvh[(size_t)DIM * NQKV];     // fp16 [K, Nq|Nk|Nv]
__device__ __half g_woh  [(size_t)DIM * DIM];
__device__ __half g_xqh  [(size_t)NTOK * DIM];     // fp16 post-rope Q
__device__ __half g_xkh  [(size_t)NTOK * KVDIM];   // fp16 post-rope K
__device__ __half g_xvh  [(size_t)NTOK * KVDIM];   // fp16 V
__device__ __half g_aoh  [(size_t)NTOK * DIM];     // fp16 attention output

// ---------------- cp.async helpers -----------------------------------------
__device__ __forceinline__ void cp16h(__half* smem_dst, const __half* gsrc) {
    uint32_t dst = (uint32_t)__cvta_generic_to_shared(smem_dst);
    asm volatile("cp.async.cg.shared.global [%0], [%1], 16;\n" :: "r"(dst), "l"(gsrc));
}
#define CP_COMMIT() asm volatile("cp.async.commit_group;\n" ::: "memory")
#define CP_WAIT1()  asm volatile("cp.async.wait_group 1;\n" ::: "memory")
#define CP_WAIT0()  asm volatile("cp.async.wait_group 0;\n" ::: "memory")

// ---------------- GEMM tiling constants ------------------------------------
#define GBM 128
#define GBN 256
#define GBK 32
#define GST 3
#define GA_LD 40                                     // halves: 32 + 8 pad
#define GB_LD 264                                    // halves: 256 + 8 pad
#define GA_STAGE (GBM * GA_LD)                       // 5120 halves
#define GB_STAGE (GBK * GB_LD)                       // 8448 halves
#define GSMEM_BYTES (GST * (GA_STAGE + GB_STAGE) * 2)    // 81408 B
#define STG_LD 264                                   // floats, epilogue staging
#define QKV_SMEM_BYTES (GBM * STG_LD * 4)            // 135168 B > GSMEM_BYTES

// ============================================================================
// Shared GEMM mainloop: accumulates C tile (128x256) for row-major fp16 A,B.
// ============================================================================
#define GEMM_MAINLOOP(A, B, N_, K_)                                               \
    __half* sA = smh;                                                             \
    __half* sB = smh + GST * GA_STAGE;                                            \
    const int tid  = threadIdx.x;                                                 \
    const int warp = tid >> 5;                                                    \
    const int wm   = warp >> 2;                                                   \
    const int wn   = warp & 3;                                                    \
    const int bm   = blockIdx.y * GBM;                                            \
    const int bn   = blockIdx.x * GBN;                                            \
    const int KT   = (K_) / GBK;                                                  \
    wmma::fragment<wmma::accumulator, 16, 16, 16, float> acc[4][4];               \
    _Pragma("unroll")                                                             \
    for (int i = 0; i < 4; i++)                                                   \
        _Pragma("unroll")                                                         \
        for (int j = 0; j < 4; j++) wmma::fill_fragment(acc[i][j], 0.0f);         \
    auto issue = [&](int kt, int stage) {                                         \
        __half* sa = sA + stage * GA_STAGE;                                       \
        _Pragma("unroll")                                                         \
        for (int u = 0; u < 2; u++) {                                             \
            int idx = tid + u * 256;                                              \
            int r = idx >> 2, c = (idx & 3) * 8;                                  \
            cp16h(&sa[r * GA_LD + c], (A) + (size_t)(bm + r) * (K_) + kt * GBK + c); \
        }                                                                         \
        __half* sb = sB + stage * GB_STAGE;                                       \
        _Pragma("unroll")                                                         \
        for (int u = 0; u < 4; u++) {                                             \
            int idx = tid + u * 256;                                              \
            int r = idx >> 5, c = (idx & 31) * 8;                                 \
            cp16h(&sb[r * GB_LD + c], (B) + (size_t)(kt * GBK + r) * (N_) + bn + c); \
        }                                                                         \
    };                                                                            \
    issue(0, 0); CP_COMMIT();                                                     \
    issue(1, 1); CP_COMMIT();                                                     \
    for (int kt = 0; kt < KT; kt++) {                                             \
        CP_WAIT1();                                                               \
        __syncthreads();                                                          \
        if (kt + 2 < KT) issue(kt + 2, (kt + 2) % GST);                           \
        CP_COMMIT();                                                              \
        const __half* sa = sA + (kt % GST) * GA_STAGE;                            \
        const __half* sb = sB + (kt % GST) * GB_STAGE;                            \
        _Pragma("unroll")                                                         \
        for (int ks = 0; ks < 2; ks++) {                                          \
            wmma::fragment<wmma::matrix_a, 16, 16, 16, __half, wmma::row_major> af[4]; \
            wmma::fragment<wmma::matrix_b, 16, 16, 16, __half, wmma::row_major> bf[4]; \
            _Pragma("unroll")                                                     \
            for (int i = 0; i < 4; i++)                                           \
                wmma::load_matrix_sync(af[i], &sa[(wm * 64 + i * 16) * GA_LD + ks * 16], GA_LD); \
            _Pragma("unroll")                                                     \
            for (int j = 0; j < 4; j++)                                           \
                wmma::load_matrix_sync(bf[j], &sb[(ks * 16) * GB_LD + wn * 64 + j * 16], GB_LD); \
            _Pragma("unroll")                                                     \
            for (int i = 0; i < 4; i++)                                           \
                _Pragma("unroll")                                                 \
                for (int j = 0; j < 4; j++)                                       \
                    wmma::mma_sync(acc[i][j], af[i], bf[j], acc[i][j]);           \
        }                                                                         \
    }

// ============================================================================
// Fused QKV projection GEMM: C = xh[4096,4096] * wqkv[4096,6144], epilogue
// applies RoPE (Q,K regions) and writes fp16 directly. Column blocks (256)
// never straddle the Q/K/V boundaries (multiples of 1024) -> uniform branch.
// ============================================================================
__global__ __launch_bounds__(256, 1)
void gemm_qkv(const __half* __restrict__ A, const __half* __restrict__ B,
              const float* __restrict__ fc, const float* __restrict__ fs,
              __half* __restrict__ xq, __half* __restrict__ xk,
              __half* __restrict__ xv)
{
    extern __shared__ __half smh[];
    GEMM_MAINLOOP(A, B, NQKV, DIM)

    // drain pending (empty) cp.async groups, then reuse smem for staging
    CP_WAIT0();
    __syncthreads();
    float* stg = (float*)smh;            // 128 x 264 floats
#pragma unroll
    for (int i = 0; i < 4; i++)
#pragma unroll
        for (int j = 0; j < 4; j++)
            wmma::store_matrix_sync(&stg[(wm * 64 + i * 16) * STG_LD + wn * 64 + j * 16],
                                    acc[i][j], STG_LD, wmma::mem_row_major);
    __syncthreads();

    const int region = (bn < DIM) ? 0 : (bn < DIM + KVDIM ? 1 : 2);
#pragma unroll
    for (int it = 0; it < 64; it++) {
        const int idx = tid + it * 256;          // 16384 float2 slots
        const int r   = idx >> 7;
        const int c2  = idx & 127;
        const float2 v = *(const float2*)&stg[r * STG_LD + 2 * c2];
        const int tok = bm + r;
        const int n0  = bn + 2 * c2;
        __half2 hv;
        if (region == 2) {
            hv = __floats2half2_rn(v.x, v.y);
            *(__half2*)(xv + (size_t)tok * KVDIM + (n0 - DIM - KVDIM)) = hv;
        } else {
            const int s = tok & (SEQL - 1);
            const int i = (n0 & (HD - 1)) >> 1;
            const float c  = fc[s * 64 + i];
            const float sn = fs[s * 64 + i];
            hv = __floats2half2_rn(v.x * c - v.y * sn, v.x * sn + v.y * c);
            if (region == 0) *(__half2*)(xq + (size_t)tok * DIM + n0) = hv;
            else             *(__half2*)(xk + (size_t)tok * KVDIM + (n0 - DIM)) = hv;
        }
    }
}

// ============================================================================
// Plain fp16 GEMM with fp32 output (wo projection).
// ============================================================================
__global__ __launch_bounds__(256, 1)
void gemm_fp16(const __half* __restrict__ A, const __half* __restrict__ B,
               float* __restrict__ C, int M, int N, int K)
{
    extern __shared__ __half smh[];
    GEMM_MAINLOOP(A, B, N, K)

#pragma unroll
    for (int i = 0; i < 4; i++)
#pragma unroll
        for (int j = 0; j < 4; j++) {
            float* cp = C + (size_t)(bm + wm * 64 + i * 16) * N + bn + wn * 64 + j * 16;
            wmma::store_matrix_sync(cp, acc[i][j], N, wmma::mem_row_major);
        }
}

// ---------------- fp32 -> fp16 converts -------------------------------------
__global__ void to_half(const float* __restrict__ src, __half* __restrict__ dst)
{
    const size_t i = ((size_t)blockIdx.x * blockDim.x + threadIdx.x) * 4;
    float4 v = *(const float4*)(src + i);
    *(__half2*)(dst + i)     = __floats2half2_rn(v.x, v.y);
    *(__half2*)(dst + i + 2) = __floats2half2_rn(v.z, v.w);
}

// src is [R, 1<<cshift] contiguous; dst row stride dstld, column offset coloff
__global__ void to_half_slice(const float* __restrict__ src, __half* __restrict__ dst,
                              int cshift, int dstld, int coloff)
{
    const size_t i = ((size_t)blockIdx.x * blockDim.x + threadIdx.x) * 4;
    const int r = (int)(i >> cshift);
    const int c = (int)(i & ((1u << cshift) - 1));
    float4 v = *(const float4*)(src + i);
    __half* d = dst + (size_t)r * dstld + coloff + c;
    *(__half2*)(d)     = __floats2half2_rn(v.x, v.y);
    *(__half2*)(d + 2) = __floats2half2_rn(v.z, v.w);
}

// ============================================================================
// Causal attention, FP16 WMMA (m16n16k16, fp32 acc), flash-style streaming,
// no-rescale softmax. Q-tile 128 (Q in register frags), KV-tile 64, 2-stage
// cp.async K/V. grid: (SEQL/128, NH, BSZ), 256 threads.  (unchanged from R13)
// ============================================================================
#define KV_LD 136
#define KV_BLOCK_H (64 * KV_LD)
#define KV_STAGE_H (2 * KV_BLOCK_H)
#define ARENA_BYTES (2 * KV_STAGE_H * 2)
#define SS_BYTE   ARENA_BYTES
#define SP_BYTE   (SS_BYTE + 128 * 72 * 4)
#define SL_BYTE   (SP_BYTE + 128 * 80 * 2)
#define ATT_SMEM_BYTES (SL_BYTE + 512)

__global__ __launch_bounds__(256)
void attn_kernel(const __half* __restrict__ xq, const __half* __restrict__ xk,
                 const __half* __restrict__ xv, __half* __restrict__ ao)
{
    extern __shared__ char smraw[];
    __half* smh = (__half*)smraw;
    float*  sS  = (float*)(smraw + SS_BYTE);
    __half* sP  = (__half*)(smraw + SP_BYTE);
    float*  sL  = (float*)(smraw + SL_BYTE);

    const int tid  = threadIdx.x;
    const int warp = tid >> 5;
    const int b    = blockIdx.z;
    const int h    = blockIdx.y;
    const int qt   = gridDim.x - 1 - blockIdx.x;
    const int q0   = qt * 128;
    const int kvh  = h >> 2;
    const int NT   = 2 * (qt + 1);
    const float scale = 0.08838834764831845f;

    {
        const __half* src = xq + ((size_t)(b * SEQL + q0)) * DIM + h * HD;
#pragma unroll
        for (int it = 0; it < 8; it++) {
            const int idx = tid + it * 256;
            const int r = idx >> 4, c = (idx & 15) * 8;
            *(uint4*)&smh[r * KV_LD + c] = *(const uint4*)(src + (size_t)r * DIM + c);
        }
    }
    if (tid < 128) sL[tid] = 0.0f;
    __syncthreads();

    wmma::fragment<wmma::matrix_a, 16, 16, 16, __half, wmma::row_major> qf[8];
#pragma unroll
    for (int k16 = 0; k16 < 8; k16++)
        wmma::load_matrix_sync(qf[k16], &smh[(warp * 16) * KV_LD + k16 * 16], KV_LD);
    __syncthreads();

    wmma::fragment<wmma::accumulator, 16, 16, 16, float> accO[8];
#pragma unroll
    for (int j = 0; j < 8; j++) wmma::fill_fragment(accO[j], 0.0f);

    auto issueKV = [&](int kt, int stage) {
        const __half* ksrc = xk + ((size_t)(b * SEQL + kt * 64)) * KVDIM + kvh * HD;
        const __half* vsrc = xv + ((size_t)(b * SEQL + kt * 64)) * KVDIM + kvh * HD;
        __half* sk = smh + stage * KV_STAGE_H;
        __half* sv = sk + KV_BLOCK_H;
#pragma unroll
        for (int u = 0; u < 4; u++) {
            int idx = tid + u * 256;
            int r = idx >> 4, c = (idx & 15) * 8;
            cp16h(&sk[r * KV_LD + c], ksrc + (size_t)r * KVDIM + c);
            cp16h(&sv[r * KV_LD + c], vsrc + (size_t)r * KVDIM + c);
        }
    };

    issueKV(0, 0); CP_COMMIT();

    for (int kt = 0; kt < NT; kt++) {
        if (kt + 1 < NT) issueKV(kt + 1, (kt + 1) & 1);
        CP_COMMIT();
        CP_WAIT1();
        __syncthreads();

        const __half* sK = smh + (kt & 1) * KV_STAGE_H;
        const __half* sV = sK + KV_BLOCK_H;

        wmma::fragment<wmma::accumulator, 16, 16, 16, float> accS[4];
#pragma unroll
        for (int j = 0; j < 4; j++) wmma::fill_fragment(accS[j], 0.0f);
#pragma unroll
        for (int k16 = 0; k16 < 8; k16++) {
#pragma unroll
            for (int j = 0; j < 4; j++) {
                wmma::fragment<wmma::matrix_b, 16, 16, 16, __half, wmma::col_major> bf;
                wmma::load_matrix_sync(bf, &sK[(j * 16) * KV_LD + k16 * 16], KV_LD);
                wmma::mma_sync(accS[j], qf[k16], bf, accS[j]);
            }
        }
#pragma unroll
        for (int j = 0; j < 4; j++)
            wmma::store_matrix_sync(&sS[(warp * 16) * 72 + j * 16], accS[j], 72,
                                    wmma::mem_row_major);
        __syncthreads();

        {
            const int r  = tid >> 1;
            const int c0 = (tid & 1) * 32;
            const int q  = q0 + r;
            const int kv0 = kt * 64;
            const bool need_mask = (kt >= 2 * qt);
            float part = 0.0f;
#pragma unroll
            for (int cc = 0; cc < 32; cc++) {
                const int c = c0 + cc;
                float s = sS[r * 72 + c] * scale;
                float p = (need_mask && (kv0 + c > q)) ? 0.0f : __expf(s);
                __half ph = __float2half_rn(p);
                sP[r * 80 + c] = ph;
                part += __half2float(ph);
            }
            part += __shfl_xor_sync(0xffffffffu, part, 1);
            if ((tid & 1) == 0) sL[r] += part;
        }
        __syncthreads();

#pragma unroll
        for (int k16 = 0; k16 < 4; k16++) {
            wmma::fragment<wmma::matrix_a, 16, 16, 16, __half, wmma::row_major> af;
            wmma::load_matrix_sync(af, &sP[(warp * 16) * 80 + k16 * 16], 80);
#pragma unroll
            for (int j = 0; j < 8; j++) {
                wmma::fragment<wmma::matrix_b, 16, 16, 16, __half, wmma::row_major> bf;
                wmma::load_matrix_sync(bf, &sV[(k16 * 16) * KV_LD + j * 16], KV_LD);
                wmma::mma_sync(accO[j], af, bf, accO[j]);
            }
        }
        __syncthreads();
    }

    float* smO = (float*)smraw;
#pragma unroll
    for (int j = 0; j < 8; j++)
        wmma::store_matrix_sync(&smO[(warp * 16) * KV_LD + j * 16], accO[j], KV_LD,
                                wmma::mem_row_major);
    __syncthreads();
    {
        __half* dst = ao + ((size_t)(b * SEQL + q0)) * DIM + h * HD;
#pragma unroll
        for (int it = 0; it < 16; it++) {
            const int idx = tid + it * 256;
            const int r = idx >> 5, c = (idx & 31) * 4;
            const float inv = 1.0f / sL[r];
            float4 v = *(float4*)&smO[r * KV_LD + c];
            *(__half2*)(dst + (size_t)r * DIM + c)     = __floats2half2_rn(v.x * inv, v.y * inv);
            *(__half2*)(dst + (size_t)r * DIM + c + 2) = __floats2half2_rn(v.z * inv, v.w * inv);
        }
    }
}

// ---------------- launch ----------------------------------------------------
extern "C" void kernel_launch(void* const* d_in, const int* in_sizes, int n_in,
                              void* d_out, int out_size)
{
    const float* x  = (const float*)d_in[0];
    const float* wq = (const float*)d_in[1];
    const float* wk = (const float*)d_in[2];
    const float* wv = (const float*)d_in[3];
    const float* wo = (const float*)d_in[4];
    const float* fc = (const float*)d_in[7];
    const float* fs = (const float*)d_in[8];
    float* out = (float*)d_out;
    (void)in_sizes; (void)n_in; (void)out_size;

    __half *xh, *wqkvh, *woh, *xqh, *xkh, *xvh, *aoh;
    cudaGetSymbolAddress((void**)&xh,    g_xh);
    cudaGetSymbolAddress((void**)&wqkvh, g_wqkvh);
    cudaGetSymbolAddress((void**)&woh,   g_woh);
    cudaGetSymbolAddress((void**)&xqh,   g_xqh);
    cudaGetSymbolAddress((void**)&xkh,   g_xkh);
    cudaGetSymbolAddress((void**)&xvh,   g_xvh);
    cudaGetSymbolAddress((void**)&aoh,   g_aoh);

    cudaFuncSetAttribute(gemm_qkv, cudaFuncAttributeMaxDynamicSharedMemorySize,
                         QKV_SMEM_BYTES);
    cudaFuncSetAttribute(gemm_fp16, cudaFuncAttributeMaxDynamicSharedMemorySize,
                         GSMEM_BYTES);
    cudaFuncSetAttribute(attn_kernel, cudaFuncAttributeMaxDynamicSharedMemorySize,
                         ATT_SMEM_BYTES);

    // convert inputs to fp16; weights concatenated into [DIM, 6144]
    to_half<<<(NTOK * DIM)  / 1024, 256>>>(x,  xh);
    to_half_slice<<<(DIM * DIM)   / 1024, 256>>>(wq, wqkvh, 12, NQKV, 0);
    to_half_slice<<<(DIM * KVDIM) / 1024, 256>>>(wk, wqkvh, 10, NQKV, DIM);
    to_half_slice<<<(DIM * KVDIM) / 1024, 256>>>(wv, wqkvh, 10, NQKV, DIM + KVDIM);
    to_half<<<(DIM * DIM) / 1024, 256>>>(wo, woh);

    // fused QKV projection + RoPE + fp16 write
    gemm_qkv<<<dim3(NQKV / GBN, NTOK / GBM), 256, QKV_SMEM_BYTES>>>(
        xh, wqkvh, fc, fs, xqh, xkh, xvh);

    // causal attention (fp16 in/out)
    attn_kernel<<<dim3(SEQL / 128, NH, BSZ), 256, ATT_SMEM_BYTES>>>(xqh, xkh, xvh, aoh);

    // output projection (fp32 out)
    gemm_fp16<<<dim3(DIM / GBN, NTOK / GBM), 256, GSMEM_BYTES>>>(aoh, woh, out, NTOK, DIM, DIM);
}

// round 15
// speedup vs baseline: 1.3111x; 1.3111x over previous
#include <cuda_runtime.h>
#include <cuda_fp16.h>
#include <mma.h>
#include <cstdint>

using namespace nvcuda;

#define BSZ   2
#define SEQL  2048
#define DIM   4096
#define NH    32
#define NKV   8
#define HD    128
#define NTOK  (BSZ * SEQL)        // 4096
#define KVDIM (NKV * HD)          // 1024
#define NQKV  (DIM + 2 * KVDIM)   // 6144

// ---------------- scratch (device globals: allocation-guard safe) ----------
__device__ __half g_xh   [(size_t)NTOK * DIM];     // fp16 x
__device__ __half g_wqkvh[(size_t)DIM * NQKV];     // fp16 [K, Nq|Nk|Nv]
__device__ __half g_woh  [(size_t)DIM * DIM];
__device__ float  g_xqkv [(size_t)NTOK * NQKV];    // fp32 fused QKV GEMM out
__device__ __half g_xqh  [(size_t)NTOK * DIM];     // fp16 post-rope Q (pre-scaled)
__device__ __half g_xkh  [(size_t)NTOK * KVDIM];   // fp16 post-rope K
__device__ __half g_xvh  [(size_t)NTOK * KVDIM];   // fp16 V
__device__ __half g_aoh  [(size_t)NTOK * DIM];     // fp16 attention output

// ---------------- cp.async helpers -----------------------------------------
__device__ __forceinline__ void cp16h(__half* smem_dst, const __half* gsrc) {
    uint32_t dst = (uint32_t)__cvta_generic_to_shared(smem_dst);
    asm volatile("cp.async.cg.shared.global [%0], [%1], 16;\n" :: "r"(dst), "l"(gsrc));
}
#define CP_COMMIT() asm volatile("cp.async.commit_group;\n" ::: "memory")
#define CP_WAIT1()  asm volatile("cp.async.wait_group 1;\n" ::: "memory")

// ============================================================================
// FP16 WMMA GEMM: C[M,N](fp32) = A[M,K](fp16)*B[K,N](fp16), row-major.
// 128x128 CTA tile, 128 threads (4 warps, 64x64 each), BK=32, 3-stage
// cp.async. 2 CTAs/SM residency (smem 56.8KB, regs <= 255).
// ============================================================================
#define GBM 128
#define GBN 128
#define GBK 32
#define GST 3
#define GA_LD 40                                     // halves: 32 + 8 pad
#define GB_LD 136                                    // halves: 128 + 8 pad
#define GA_STAGE (GBM * GA_LD)                       // 5120 halves
#define GB_STAGE (GBK * GB_LD)                       // 4352 halves
#define GSMEM_BYTES (GST * (GA_STAGE + GB_STAGE) * 2)   // 56832 B

__global__ __launch_bounds__(128, 2)
void gemm_fp16(const __half* __restrict__ A, const __half* __restrict__ B,
               float* __restrict__ C, int M, int N, int K)
{
    extern __shared__ __half smh[];
    __half* sA = smh;                       // [GST][128][40]
    __half* sB = smh + GST * GA_STAGE;      // [GST][32][136]

    const int tid  = threadIdx.x;
    const int warp = tid >> 5;
    const int wm   = warp >> 1;  // 0..1  -> 64-row group
    const int wn   = warp & 1;   // 0..1  -> 64-col group
    const int bm   = blockIdx.y * GBM;
    const int bn   = blockIdx.x * GBN;
    const int KT   = K / GBK;

    wmma::fragment<wmma::accumulator, 16, 16, 16, float> acc[4][4];
#pragma unroll
    for (int i = 0; i < 4; i++)
#pragma unroll
        for (int j = 0; j < 4; j++) wmma::fill_fragment(acc[i][j], 0.0f);

    auto issue = [&](int kt, int stage) {
        __half* sa = sA + stage * GA_STAGE;
#pragma unroll
        for (int u = 0; u < 4; u++) {             // A: 128x32 halves -> 512 x16B
            int idx = tid + u * 128;
            int r = idx >> 2, c = (idx & 3) * 8;
            cp16h(&sa[r * GA_LD + c], A + (size_t)(bm + r) * K + kt * GBK + c);
        }
        __half* sb = sB + stage * GB_STAGE;
#pragma unroll
        for (int u = 0; u < 4; u++) {             // B: 32x128 halves -> 512 x16B
            int idx = tid + u * 128;
            int r = idx >> 4, c = (idx & 15) * 8;
            cp16h(&sb[r * GB_LD + c], B + (size_t)(kt * GBK + r) * N + bn + c);
        }
    };

    issue(0, 0); CP_COMMIT();
    issue(1, 1); CP_COMMIT();

    for (int kt = 0; kt < KT; kt++) {
        CP_WAIT1();
        __syncthreads();
        if (kt + 2 < KT) issue(kt + 2, (kt + 2) % GST);
        CP_COMMIT();

        const __half* sa = sA + (kt % GST) * GA_STAGE;
        const __half* sb = sB + (kt % GST) * GB_STAGE;
#pragma unroll
        for (int ks = 0; ks < 2; ks++) {
            wmma::fragment<wmma::matrix_a, 16, 16, 16, __half, wmma::row_major> af[4];
            wmma::fragment<wmma::matrix_b, 16, 16, 16, __half, wmma::row_major> bf[4];
#pragma unroll
            for (int i = 0; i < 4; i++)
                wmma::load_matrix_sync(af[i], &sa[(wm * 64 + i * 16) * GA_LD + ks * 16], GA_LD);
#pragma unroll
            for (int j = 0; j < 4; j++)
                wmma::load_matrix_sync(bf[j], &sb[(ks * 16) * GB_LD + wn * 64 + j * 16], GB_LD);
#pragma unroll
            for (int i = 0; i < 4; i++)
#pragma unroll
                for (int j = 0; j < 4; j++)
                    wmma::mma_sync(acc[i][j], af[i], bf[j], acc[i][j]);
        }
    }

#pragma unroll
    for (int i = 0; i < 4; i++)
#pragma unroll
        for (int j = 0; j < 4; j++) {
            float* cp = C + (size_t)(bm + wm * 64 + i * 16) * N + bn + wn * 64 + j * 16;
            wmma::store_matrix_sync(cp, acc[i][j], N, wmma::mem_row_major);
        }
}

// ---------------- fp32 -> fp16 converts -------------------------------------
__global__ void to_half(const float* __restrict__ src, __half* __restrict__ dst)
{
    const size_t i = ((size_t)blockIdx.x * blockDim.x + threadIdx.x) * 4;
    float4 v = *(const float4*)(src + i);
    *(__half2*)(dst + i)     = __floats2half2_rn(v.x, v.y);
    *(__half2*)(dst + i + 2) = __floats2half2_rn(v.z, v.w);
}

// src [R, 1<<cshift] contiguous -> dst row stride dstld at column offset coloff
__global__ void to_half_slice(const float* __restrict__ src, __half* __restrict__ dst,
                              int cshift, int dstld, int coloff)
{
    const size_t i = ((size_t)blockIdx.x * blockDim.x + threadIdx.x) * 4;
    const int r = (int)(i >> cshift);
    const int c = (int)(i & ((1u << cshift) - 1));
    float4 v = *(const float4*)(src + i);
    __half* d = dst + (size_t)r * dstld + coloff + c;
    *(__half2*)(d)     = __floats2half2_rn(v.x, v.y);
    *(__half2*)(d + 2) = __floats2half2_rn(v.z, v.w);
}

// src strided slice [R, 1024 @ coloff, row stride srcld] -> dst contiguous fp16
__global__ void to_half_gslice(const float* __restrict__ src, int srcld, int coloff,
                               __half* __restrict__ dst)
{
    const size_t i = ((size_t)blockIdx.x * blockDim.x + threadIdx.x) * 4;
    const int r = (int)(i >> 10);
    const int c = (int)(i & 1023u);
    float4 v = *(const float4*)(src + (size_t)r * srcld + coloff + c);
    *(__half2*)(dst + i)     = __floats2half2_rn(v.x, v.y);
    *(__half2*)(dst + i + 2) = __floats2half2_rn(v.z, v.w);
}

// ---------------- RoPE: fp32 strided slice in, fp16 out, optional scale ----
__global__ void rope_half(const float* __restrict__ src, int srcld,
                          __half* __restrict__ dst, int dstld,
                          const float* __restrict__ fc, const float* __restrict__ fs,
                          int nh, float scale)
{
    const int idx  = blockIdx.x * blockDim.x + threadIdx.x;
    const int i    = idx & 63;
    const int rest = idx >> 6;
    const int h    = rest % nh;
    const int tok  = rest / nh;
    const int s    = tok & (SEQL - 1);

    const float c  = fc[s * 64 + i];
    const float sn = fs[s * 64 + i];

    const float2 v = *(const float2*)(src + (size_t)tok * srcld + h * HD + 2 * i);
    float ox = (v.x * c - v.y * sn) * scale;
    float oy = (v.x * sn + v.y * c) * scale;
    *((__half2*)(dst + (size_t)tok * dstld + h * HD) + i) = __floats2half2_rn(ox, oy);
}

// ============================================================================
// Causal attention, FP16 WMMA, flash-style, no-rescale softmax.
// Q pre-scaled by 1/sqrt(HD). Warp-local softmax (no CTA barriers around it).
// Q-tile 128 (Q in register frags), KV-tile 64, 2-stage cp.async K/V.
// grid: (SEQL/128, NH, BSZ), 256 threads (8 warps).
// ============================================================================
#define KV_LD 136
#define KV_BLOCK_H (64 * KV_LD)
#define KV_STAGE_H (2 * KV_BLOCK_H)
#define ARENA_BYTES (2 * KV_STAGE_H * 2)
#define SS_BYTE   ARENA_BYTES
#define SP_BYTE   (SS_BYTE + 128 * 72 * 4)
#define SL_BYTE   (SP_BYTE + 128 * 80 * 2)
#define ATT_SMEM_BYTES (SL_BYTE + 512)

__global__ __launch_bounds__(256)
void attn_kernel(const __half* __restrict__ xq, const __half* __restrict__ xk,
                 const __half* __restrict__ xv, __half* __restrict__ ao)
{
    extern __shared__ char smraw[];
    __half* smh = (__half*)smraw;
    float*  sS  = (float*)(smraw + SS_BYTE);
    __half* sP  = (__half*)(smraw + SP_BYTE);
    float*  sL  = (float*)(smraw + SL_BYTE);

    const int tid  = threadIdx.x;
    const int warp = tid >> 5;
    const int lane = tid & 31;
    const int b    = blockIdx.z;
    const int h    = blockIdx.y;
    const int qt   = gridDim.x - 1 - blockIdx.x;   // heavy tiles first
    const int q0   = qt * 128;
    const int kvh  = h >> 2;                       // N_REP = 4
    const int NT   = 2 * (qt + 1);

    {
        const __half* src = xq + ((size_t)(b * SEQL + q0)) * DIM + h * HD;
#pragma unroll
        for (int it = 0; it < 8; it++) {
            const int idx = tid + it * 256;
            const int r = idx >> 4, c = (idx & 15) * 8;
            *(uint4*)&smh[r * KV_LD + c] = *(const uint4*)(src + (size_t)r * DIM + c);
        }
    }
    if (tid < 128) sL[tid] = 0.0f;
    __syncthreads();

    wmma::fragment<wmma::matrix_a, 16, 16, 16, __half, wmma::row_major> qf[8];
#pragma unroll
    for (int k16 = 0; k16 < 8; k16++)
        wmma::load_matrix_sync(qf[k16], &smh[(warp * 16) * KV_LD + k16 * 16], KV_LD);
    __syncthreads();

    wmma::fragment<wmma::accumulator, 16, 16, 16, float> accO[8];
#pragma unroll
    for (int j = 0; j < 8; j++) wmma::fill_fragment(accO[j], 0.0f);

    auto issueKV = [&](int kt, int stage) {
        const __half* ksrc = xk + ((size_t)(b * SEQL + kt * 64)) * KVDIM + kvh * HD;
        const __half* vsrc = xv + ((size_t)(b * SEQL + kt * 64)) * KVDIM + kvh * HD;
        __half* sk = smh + stage * KV_STAGE_H;
        __half* sv = sk + KV_BLOCK_H;
#pragma unroll
        for (int u = 0; u < 4; u++) {
            int idx = tid + u * 256;
            int r = idx >> 4, c = (idx & 15) * 8;
            cp16h(&sk[r * KV_LD + c], ksrc + (size_t)r * KVDIM + c);
            cp16h(&sv[r * KV_LD + c], vsrc + (size_t)r * KVDIM + c);
        }
    };

    issueKV(0, 0); CP_COMMIT();

    for (int kt = 0; kt < NT; kt++) {
        if (kt + 1 < NT) issueKV(kt + 1, (kt + 1) & 1);
        CP_COMMIT();
        CP_WAIT1();
        __syncthreads();

        const __half* sK = smh + (kt & 1) * KV_STAGE_H;
        const __half* sV = sK + KV_BLOCK_H;

        // ---- S = Q K^T (warp: own 16 rows x 64 cols, k=128)
        wmma::fragment<wmma::accumulator, 16, 16, 16, float> accS[4];
#pragma unroll
        for (int j = 0; j < 4; j++) wmma::fill_fragment(accS[j], 0.0f);
#pragma unroll
        for (int k16 = 0; k16 < 8; k16++) {
#pragma unroll
            for (int j = 0; j < 4; j++) {
                wmma::fragment<wmma::matrix_b, 16, 16, 16, __half, wmma::col_major> bf;
                wmma::load_matrix_sync(bf, &sK[(j * 16) * KV_LD + k16 * 16], KV_LD);
                wmma::mma_sync(accS[j], qf[k16], bf, accS[j]);
            }
        }
#pragma unroll
        for (int j = 0; j < 4; j++)
            wmma::store_matrix_sync(&sS[(warp * 16) * 72 + j * 16], accS[j], 72,
                                    wmma::mem_row_major);
        __syncwarp();   // warp-private rows: warp barrier suffices

        // ---- P = fp16(exp(S)) with causal mask (Q pre-scaled); fp32 row sums
        {
            const int r  = warp * 16 + (lane >> 1);
            const int c0 = (lane & 1) * 32;
            const int q  = q0 + r;
            const int kv0 = kt * 64;
            const bool need_mask = (kt >= 2 * qt);
            float part = 0.0f;
#pragma unroll
            for (int cc = 0; cc < 32; cc++) {
                const int c = c0 + cc;
                float s = sS[r * 72 + c];
                float p = (need_mask && (kv0 + c > q)) ? 0.0f : __expf(s);
                __half ph = __float2half_rn(p);
                sP[r * 80 + c] = ph;
                part += __half2float(ph);
            }
            part += __shfl_xor_sync(0xffffffffu, part, 1);
            if ((lane & 1) == 0) sL[r] += part;
        }
        __syncwarp();   // sP rows consumed only by this warp's af loads

        // ---- O += P V  (warp: own 16 rows x 128 cols, k=64)
#pragma unroll
        for (int k16 = 0; k16 < 4; k16++) {
            wmma::fragment<wmma::matrix_a, 16, 16, 16, __half, wmma::row_major> af;
            wmma::load_matrix_sync(af, &sP[(warp * 16) * 80 + k16 * 16], 80);
#pragma unroll
            for (int j = 0; j < 8; j++) {
                wmma::fragment<wmma::matrix_b, 16, 16, 16, __half, wmma::row_major> bf;
                wmma::load_matrix_sync(bf, &sV[(k16 * 16) * KV_LD + j * 16], KV_LD);
                wmma::mma_sync(accO[j], af, bf, accO[j]);
            }
        }
        __syncthreads();   // KV stage free before next issue overwrites
    }

    float* smO = (float*)smraw;
#pragma unroll
    for (int j = 0; j < 8; j++)
        wmma::store_matrix_sync(&smO[(warp * 16) * KV_LD + j * 16], accO[j], KV_LD,
                                wmma::mem_row_major);
    __syncthreads();
    {
        __half* dst = ao + ((size_t)(b * SEQL + q0)) * DIM + h * HD;
#pragma unroll
        for (int it = 0; it < 16; it++) {
            const int idx = tid + it * 256;
            const int r = idx >> 5, c = (idx & 31) * 4;
            const float inv = 1.0f / sL[r];
            float4 v = *(float4*)&smO[r * KV_LD + c];
            *(__half2*)(dst + (size_t)r * DIM + c)     = __floats2half2_rn(v.x * inv, v.y * inv);
            *(__half2*)(dst + (size_t)r * DIM + c + 2) = __floats2half2_rn(v.z * inv, v.w * inv);
        }
    }
}

// ---------------- launch ----------------------------------------------------
extern "C" void kernel_launch(void* const* d_in, const int* in_sizes, int n_in,
                              void* d_out, int out_size)
{
    const float* x  = (const float*)d_in[0];
    const float* wq = (const float*)d_in[1];
    const float* wk = (const float*)d_in[2];
    const float* wv = (const float*)d_in[3];
    const float* wo = (const float*)d_in[4];
    const float* fc = (const float*)d_in[7];
    const float* fs = (const float*)d_in[8];
    float* out = (float*)d_out;
    (void)in_sizes; (void)n_in; (void)out_size;

    __half *xh, *wqkvh, *woh, *xqh, *xkh, *xvh, *aoh;
    float *xqkv;
    cudaGetSymbolAddress((void**)&xh,    g_xh);
    cudaGetSymbolAddress((void**)&wqkvh, g_wqkvh);
    cudaGetSymbolAddress((void**)&woh,   g_woh);
    cudaGetSymbolAddress((void**)&xqkv,  g_xqkv);
    cudaGetSymbolAddress((void**)&xqh,   g_xqh);
    cudaGetSymbolAddress((void**)&xkh,   g_xkh);
    cudaGetSymbolAddress((void**)&xvh,   g_xvh);
    cudaGetSymbolAddress((void**)&aoh,   g_aoh);

    cudaFuncSetAttribute(gemm_fp16, cudaFuncAttributeMaxDynamicSharedMemorySize,
                         GSMEM_BYTES);
    cudaFuncSetAttribute(attn_kernel, cudaFuncAttributeMaxDynamicSharedMemorySize,
                         ATT_SMEM_BYTES);

    // convert inputs to fp16; weights concatenated into [DIM, 6144]
    to_half<<<(NTOK * DIM)  / 1024, 256>>>(x,  xh);
    to_half_slice<<<(DIM * DIM)   / 1024, 256>>>(wq, wqkvh, 12, NQKV, 0);
    to_half_slice<<<(DIM * KVDIM) / 1024, 256>>>(wk, wqkvh, 10, NQKV, DIM);
    to_half_slice<<<(DIM * KVDIM) / 1024, 256>>>(wv, wqkvh, 10, NQKV, DIM + KVDIM);
    to_half<<<(DIM * DIM) / 1024, 256>>>(wo, woh);

    // fused QKV projection (fp32 out), 1536 CTAs @ 2/SM
    gemm_fp16<<<dim3(NQKV / GBN, NTOK / GBM), 128, GSMEM_BYTES>>>(
        xh, wqkvh, xqkv, NTOK, NQKV, DIM);

    // RoPE Q (folds 1/sqrt(HD) scale), RoPE K, convert V
    const float scale = 0.08838834764831845f;
    rope_half<<<(NTOK * NH  * 64) / 256, 256>>>(xqkv, NQKV, xqh, DIM,   fc, fs, NH,  scale);
    rope_half<<<(NTOK * NKV * 64) / 256, 256>>>(xqkv + DIM, NQKV, xkh, KVDIM, fc, fs, NKV, 1.0f);
    to_half_gslice<<<(NTOK * KVDIM) / 1024, 256>>>(xqkv, NQKV, DIM + KVDIM, xvh);

    // causal attention (fp16 in/out)
    attn_kernel<<<dim3(SEQL / 128, NH, BSZ), 256, ATT_SMEM_BYTES>>>(xqh, xkh, xvh, aoh);

    // output projection (fp32 out), 1024 CTAs @ 2/SM
    gemm_fp16<<<dim3(DIM / GBN, NTOK / GBM), 128, GSMEM_BYTES>>>(aoh, woh, out, NTOK, DIM, DIM);
}

// round 16
// speedup vs baseline: 1.5226x; 1.1613x over previous
#include <cuda_runtime.h>
#include <cuda_fp16.h>
#include <mma.h>
#include <cstdint>

using namespace nvcuda;

#define BSZ   2
#define SEQL  2048
#define DIM   4096
#define NH    32
#define NKV   8
#define HD    128
#define NTOK  (BSZ * SEQL)        // 4096
#define KVDIM (NKV * HD)          // 1024
#define NQKV  (DIM + 2 * KVDIM)   // 6144
#define QSCALE 0.08838834764831845f   // 1/sqrt(128)

// ---------------- scratch (device globals: allocation-guard safe) ----------
__device__ __half g_xh   [(size_t)NTOK * DIM];     // fp16 x
__device__ __half g_wqkvh[(size_t)DIM * NQKV];     // fp16 [K, Nq|Nk|Nv]
__device__ __half g_woh  [(size_t)DIM * DIM];
__device__ __half g_xqh  [(size_t)NTOK * DIM];     // fp16 post-rope Q (pre-scaled)
__device__ __half g_xkh  [(size_t)NTOK * KVDIM];   // fp16 post-rope K
__device__ __half g_xvh  [(size_t)NTOK * KVDIM];   // fp16 V
__device__ __half g_aoh  [(size_t)NTOK * DIM];     // fp16 attention output

// ---------------- cp.async helpers -----------------------------------------
__device__ __forceinline__ void cp16h(__half* smem_dst, const __half* gsrc) {
    uint32_t dst = (uint32_t)__cvta_generic_to_shared(smem_dst);
    asm volatile("cp.async.cg.shared.global [%0], [%1], 16;\n" :: "r"(dst), "l"(gsrc));
}
#define CP_COMMIT() asm volatile("cp.async.commit_group;\n" ::: "memory")
#define CP_WAIT1()  asm volatile("cp.async.wait_group 1;\n" ::: "memory")

// ---------------- GEMM tiling: 128x128 CTA, 128 thr (4 warps), 2 CTA/SM ----
#define GBM 128
#define GBN 128
#define GBK 32
#define GST 3
#define GA_LD 40
#define GB_LD 136
#define GA_STAGE (GBM * GA_LD)                       // 5120 halves
#define GB_STAGE (GBK * GB_LD)                       // 4352 halves
#define GSMEM_BYTES (GST * (GA_STAGE + GB_STAGE) * 2)   // 56832 B

// Shared mainloop (identical to R15): leaves acc[4][4] ready, vars bound.
#define GEMM_MAINLOOP(A, B, N_, K_)                                               \
    __half* sA = smh;                                                             \
    __half* sB = smh + GST * GA_STAGE;                                            \
    const int tid  = threadIdx.x;                                                 \
    const int warp = tid >> 5;                                                    \
    const int lane = tid & 31;                                                    \
    const int wm   = warp >> 1;                                                   \
    const int wn   = warp & 1;                                                    \
    const int bm   = blockIdx.y * GBM;                                            \
    const int bn   = blockIdx.x * GBN;                                            \
    const int KT   = (K_) / GBK;                                                  \
    (void)lane;                                                                   \
    wmma::fragment<wmma::accumulator, 16, 16, 16, float> acc[4][4];               \
    _Pragma("unroll")                                                             \
    for (int i = 0; i < 4; i++)                                                   \
        _Pragma("unroll")                                                         \
        for (int j = 0; j < 4; j++) wmma::fill_fragment(acc[i][j], 0.0f);         \
    auto issue = [&](int kt, int stage) {                                         \
        __half* sa = sA + stage * GA_STAGE;                                       \
        _Pragma("unroll")                                                         \
        for (int u = 0; u < 4; u++) {                                             \
            int idx = tid + u * 128;                                              \
            int r = idx >> 2, c = (idx & 3) * 8;                                  \
            cp16h(&sa[r * GA_LD + c], (A) + (size_t)(bm + r) * (K_) + kt * GBK + c); \
        }                                                                         \
        __half* sb = sB + stage * GB_STAGE;                                       \
        _Pragma("unroll")                                                         \
        for (int u = 0; u < 4; u++) {                                             \
            int idx = tid + u * 128;                                              \
            int r = idx >> 4, c = (idx & 15) * 8;                                 \
            cp16h(&sb[r * GB_LD + c], (B) + (size_t)(kt * GBK + r) * (N_) + bn + c); \
        }                                                                         \
    };                                                                            \
    issue(0, 0); CP_COMMIT();                                                     \
    issue(1, 1); CP_COMMIT();                                                     \
    for (int kt = 0; kt < KT; kt++) {                                             \
        CP_WAIT1();                                                               \
        __syncthreads();                                                          \
        if (kt + 2 < KT) issue(kt + 2, (kt + 2) % GST);                           \
        CP_COMMIT();                                                              \
        const __half* sa = sA + (kt % GST) * GA_STAGE;                            \
        const __half* sb = sB + (kt % GST) * GB_STAGE;                            \
        _Pragma("unroll")                                                         \
        for (int ks = 0; ks < 2; ks++) {                                          \
            wmma::fragment<wmma::matrix_a, 16, 16, 16, __half, wmma::row_major> af[4]; \
            wmma::fragment<wmma::matrix_b, 16, 16, 16, __half, wmma::row_major> bf[4]; \
            _Pragma("unroll")                                                     \
            for (int i = 0; i < 4; i++)                                           \
                wmma::load_matrix_sync(af[i], &sa[(wm * 64 + i * 16) * GA_LD + ks * 16], GA_LD); \
            _Pragma("unroll")                                                     \
            for (int j = 0; j < 4; j++)                                           \
                wmma::load_matrix_sync(bf[j], &sb[(ks * 16) * GB_LD + wn * 64 + j * 16], GB_LD); \
            _Pragma("unroll")                                                     \
            for (int i = 0; i < 4; i++)                                           \
                _Pragma("unroll")                                                 \
                for (int j = 0; j < 4; j++)                                       \
                    wmma::mma_sync(acc[i][j], af[i], bf[j], acc[i][j]);           \
        }                                                                         \
    }

// ============================================================================
// Fused QKV GEMM + in-register RoPE + fp16 writes. Column blocks (128) never
// straddle Q/K/V boundaries (4096, 5120) -> region branch is CTA-uniform.
// Relies on the m16n8k16 fp32-acc fragment layout: element pairs (2p,2p+1) =
// adjacent cols (lane%4)*2+{0,1}, rows lane/4 (+8 for odd p), n8-block +8 for
// p>=2 — exactly the RoPE pairing.
// ============================================================================
__global__ __launch_bounds__(128, 2)
void gemm_qkv(const __half* __restrict__ A, const __half* __restrict__ B,
              const float* __restrict__ fc, const float* __restrict__ fs,
              __half* __restrict__ xq, __half* __restrict__ xk,
              __half* __restrict__ xv)
{
    extern __shared__ __half smh[];
    GEMM_MAINLOOP(A, B, NQKV, DIM)

    const int region = (bn < DIM) ? 0 : (bn < DIM + KVDIM ? 1 : 2);
    const int lr = lane >> 2;          // 0..7
    const int lc = (lane & 3) * 2;     // 0,2,4,6

#pragma unroll
    for (int i = 0; i < 4; i++) {
#pragma unroll
        for (int j = 0; j < 4; j++) {
#pragma unroll
            for (int p = 0; p < 4; p++) {
                const float vx = acc[i][j].x[2 * p];
                const float vy = acc[i][j].x[2 * p + 1];
                const int tok = bm + wm * 64 + i * 16 + lr + (p & 1) * 8;
                const int n   = bn + wn * 64 + j * 16 + ((p & 2) ? 8 : 0) + lc;
                if (region == 2) {
                    *(__half2*)(xv + (size_t)tok * KVDIM + (n - DIM - KVDIM)) =
                        __floats2half2_rn(vx, vy);
                } else {
                    const int s  = tok & (SEQL - 1);
                    const int fi = (n & (HD - 1)) >> 1;
                    const float c  = fc[s * 64 + fi];
                    const float sn = fs[s * 64 + fi];
                    float ox = vx * c - vy * sn;
                    float oy = vx * sn + vy * c;
                    if (region == 0) {
                        ox *= QSCALE; oy *= QSCALE;
                        *(__half2*)(xq + (size_t)tok * DIM + n) = __floats2half2_rn(ox, oy);
                    } else {
                        *(__half2*)(xk + (size_t)tok * KVDIM + (n - DIM)) =
                            __floats2half2_rn(ox, oy);
                    }
                }
            }
        }
    }
}

// ============================================================================
// Plain fp16 GEMM with fp32 output (wo projection). Unchanged from R15.
// ============================================================================
__global__ __launch_bounds__(128, 2)
void gemm_fp16(const __half* __restrict__ A, const __half* __restrict__ B,
               float* __restrict__ C, int M, int N, int K)
{
    extern __shared__ __half smh[];
    GEMM_MAINLOOP(A, B, N, K)

#pragma unroll
    for (int i = 0; i < 4; i++)
#pragma unroll
        for (int j = 0; j < 4; j++) {
            float* cp = C + (size_t)(bm + wm * 64 + i * 16) * N + bn + wn * 64 + j * 16;
            wmma::store_matrix_sync(cp, acc[i][j], N, wmma::mem_row_major);
        }
}

// ---------------- fp32 -> fp16 converts (16 elems/thread, MLP=4) ------------
__global__ void to_half(const float* __restrict__ src, __half* __restrict__ dst)
{
    const size_t i0 = (size_t)blockIdx.x * (blockDim.x * 16) + threadIdx.x * 4;
#pragma unroll
    for (int u = 0; u < 4; u++) {
        const size_t i = i0 + (size_t)u * blockDim.x * 4;
        float4 v = *(const float4*)(src + i);
        *(__half2*)(dst + i)     = __floats2half2_rn(v.x, v.y);
        *(__half2*)(dst + i + 2) = __floats2half2_rn(v.z, v.w);
    }
}

// src [R, 1<<cshift] contiguous -> dst row stride dstld at column offset coloff
__global__ void to_half_slice(const float* __restrict__ src, __half* __restrict__ dst,
                              int cshift, int dstld, int coloff)
{
    const size_t i0 = (size_t)blockIdx.x * (blockDim.x * 16) + threadIdx.x * 4;
#pragma unroll
    for (int u = 0; u < 4; u++) {
        const size_t i = i0 + (size_t)u * blockDim.x * 4;
        const int r = (int)(i >> cshift);
        const int c = (int)(i & ((1u << cshift) - 1));
        float4 v = *(const float4*)(src + i);
        __half* d = dst + (size_t)r * dstld + coloff + c;
        *(__half2*)(d)     = __floats2half2_rn(v.x, v.y);
        *(__half2*)(d + 2) = __floats2half2_rn(v.z, v.w);
    }
}

// ============================================================================
// Causal attention, FP16 WMMA, flash-style, no-rescale softmax.
// In-register softmax on S accumulator fragments (no fp32 S staging).
// Q pre-scaled by 1/sqrt(HD). Q-tile 128 (Q in frags), KV-tile 64, 2-stage
// cp.async. grid: (SEQL/128, NH, BSZ), 256 threads (8 warps).
// ============================================================================
#define KV_LD 136
#define KV_BLOCK_H (64 * KV_LD)
#define KV_STAGE_H (2 * KV_BLOCK_H)
#define ARENA_BYTES (2 * KV_STAGE_H * 2)           // 69632 B (= O staging 128x136 f32)
#define SP_BYTE   ARENA_BYTES                      // P: 128x80 fp16
#define SL_BYTE   (SP_BYTE + 128 * 80 * 2)
#define ATT_SMEM_BYTES (SL_BYTE + 512)             // 90624 B

__global__ __launch_bounds__(256)
void attn_kernel(const __half* __restrict__ xq, const __half* __restrict__ xk,
                 const __half* __restrict__ xv, __half* __restrict__ ao)
{
    extern __shared__ char smraw[];
    __half* smh = (__half*)smraw;
    __half* sP  = (__half*)(smraw + SP_BYTE);
    float*  sL  = (float*)(smraw + SL_BYTE);

    const int tid  = threadIdx.x;
    const int warp = tid >> 5;
    const int lane = tid & 31;
    const int b    = blockIdx.z;
    const int h    = blockIdx.y;
    const int qt   = gridDim.x - 1 - blockIdx.x;   // heavy tiles first
    const int q0   = qt * 128;
    const int kvh  = h >> 2;                       // N_REP = 4
    const int NT   = 2 * (qt + 1);
    const int lr   = lane >> 2;
    const int lc   = (lane & 3) * 2;

    {
        const __half* src = xq + ((size_t)(b * SEQL + q0)) * DIM + h * HD;
#pragma unroll
        for (int it = 0; it < 8; it++) {
            const int idx = tid + it * 256;
            const int r = idx >> 4, c = (idx & 15) * 8;
            *(uint4*)&smh[r * KV_LD + c] = *(const uint4*)(src + (size_t)r * DIM + c);
        }
    }
    if (tid < 128) sL[tid] = 0.0f;
    __syncthreads();

    wmma::fragment<wmma::matrix_a, 16, 16, 16, __half, wmma::row_major> qf[8];
#pragma unroll
    for (int k16 = 0; k16 < 8; k16++)
        wmma::load_matrix_sync(qf[k16], &smh[(warp * 16) * KV_LD + k16 * 16], KV_LD);
    __syncthreads();

    wmma::fragment<wmma::accumulator, 16, 16, 16, float> accO[8];
#pragma unroll
    for (int j = 0; j < 8; j++) wmma::fill_fragment(accO[j], 0.0f);

    auto issueKV = [&](int kt, int stage) {
        const __half* ksrc = xk + ((size_t)(b * SEQL + kt * 64)) * KVDIM + kvh * HD;
        const __half* vsrc = xv + ((size_t)(b * SEQL + kt * 64)) * KVDIM + kvh * HD;
        __half* sk = smh + stage * KV_STAGE_H;
        __half* sv = sk + KV_BLOCK_H;
#pragma unroll
        for (int u = 0; u < 4; u++) {
            int idx = tid + u * 256;
            int r = idx >> 4, c = (idx & 15) * 8;
            cp16h(&sk[r * KV_LD + c], ksrc + (size_t)r * KVDIM + c);
            cp16h(&sv[r * KV_LD + c], vsrc + (size_t)r * KVDIM + c);
        }
    };

    issueKV(0, 0); CP_COMMIT();

    for (int kt = 0; kt < NT; kt++) {
        if (kt + 1 < NT) issueKV(kt + 1, (kt + 1) & 1);
        CP_COMMIT();
        CP_WAIT1();
        __syncthreads();

        const __half* sK = smh + (kt & 1) * KV_STAGE_H;
        const __half* sV = sK + KV_BLOCK_H;

        // ---- S = Q K^T (warp: own 16 rows x 64 cols, k=128)
        wmma::fragment<wmma::accumulator, 16, 16, 16, float> accS[4];
#pragma unroll
        for (int j = 0; j < 4; j++) wmma::fill_fragment(accS[j], 0.0f);
#pragma unroll
        for (int k16 = 0; k16 < 8; k16++) {
#pragma unroll
            for (int j = 0; j < 4; j++) {
                wmma::fragment<wmma::matrix_b, 16, 16, 16, __half, wmma::col_major> bf;
                wmma::load_matrix_sync(bf, &sK[(j * 16) * KV_LD + k16 * 16], KV_LD);
                wmma::mma_sync(accS[j], qf[k16], bf, accS[j]);
            }
        }

        // ---- in-register softmax: exp on fragments, fp16 P to smem, row sums
        {
            const int kv0 = kt * 64;
            const bool need_mask = (kt >= 2 * qt);
            const int row0 = warp * 16 + lr;       // p even rows
            const int q_0  = q0 + row0;
            const int q_1  = q_0 + 8;
            float sum0 = 0.0f, sum1 = 0.0f;
#pragma unroll
            for (int j = 0; j < 4; j++) {
#pragma unroll
                for (int p = 0; p < 4; p++) {
                    const int col = j * 16 + ((p & 2) ? 8 : 0) + lc;
                    const int q   = (p & 1) ? q_1 : q_0;
                    float e0 = accS[j].x[2 * p];
                    float e1 = accS[j].x[2 * p + 1];
                    e0 = (need_mask && (kv0 + col     > q)) ? 0.0f : __expf(e0);
                    e1 = (need_mask && (kv0 + col + 1 > q)) ? 0.0f : __expf(e1);
                    const __half2 hp = __floats2half2_rn(e0, e1);
                    *(__half2*)&sP[(row0 + (p & 1) * 8) * 80 + col] = hp;
                    const float2 pf = __half22float2(hp);
                    if (p & 1) sum1 += pf.x + pf.y;
                    else       sum0 += pf.x + pf.y;
                }
            }
            sum0 += __shfl_xor_sync(0xffffffffu, sum0, 1);
            sum0 += __shfl_xor_sync(0xffffffffu, sum0, 2);
            sum1 += __shfl_xor_sync(0xffffffffu, sum1, 1);
            sum1 += __shfl_xor_sync(0xffffffffu, sum1, 2);
            if ((lane & 3) == 0) {
                sL[row0]     += sum0;
                sL[row0 + 8] += sum1;
            }
        }
        __syncwarp();   // sP rows are warp-private (written+read by this warp)

        // ---- O += P V  (warp: own 16 rows x 128 cols, k=64)
#pragma unroll
        for (int k16 = 0; k16 < 4; k16++) {
            wmma::fragment<wmma::matrix_a, 16, 16, 16, __half, wmma::row_major> af;
            wmma::load_matrix_sync(af, &sP[(warp * 16) * 80 + k16 * 16], 80);
#pragma unroll
            for (int j = 0; j < 8; j++) {
                wmma::fragment<wmma::matrix_b, 16, 16, 16, __half, wmma::row_major> bf;
                wmma::load_matrix_sync(bf, &sV[(k16 * 16) * KV_LD + j * 16], KV_LD);
                wmma::mma_sync(accO[j], af, bf, accO[j]);
            }
        }
        __syncthreads();   // KV stage free before next issue overwrites
    }

    // ---- epilogue: stage O (fp32, arena), divide by row sums, fp16 out
    float* smO = (float*)smraw;
#pragma unroll
    for (int j = 0; j < 8; j++)
        wmma::store_matrix_sync(&smO[(warp * 16) * KV_LD + j * 16], accO[j], KV_LD,
                                wmma::mem_row_major);
    __syncthreads();
    {
        __half* dst = ao + ((size_t)(b * SEQL + q0)) * DIM + h * HD;
#pragma unroll
        for (int it = 0; it < 16; it++) {
            const int idx = tid + it * 256;
            const int r = idx >> 5, c = (idx & 31) * 4;
            const float inv = 1.0f / sL[r];
            float4 v = *(float4*)&smO[r * KV_LD + c];
            *(__half2*)(dst + (size_t)r * DIM + c)     = __floats2half2_rn(v.x * inv, v.y * inv);
            *(__half2*)(dst + (size_t)r * DIM + c + 2) = __floats2half2_rn(v.z * inv, v.w * inv);
        }
    }
}

// ---------------- launch ----------------------------------------------------
extern "C" void kernel_launch(void* const* d_in, const int* in_sizes, int n_in,
                              void* d_out, int out_size)
{
    const float* x  = (const float*)d_in[0];
    const float* wq = (const float*)d_in[1];
    const float* wk = (const float*)d_in[2];
    const float* wv = (const float*)d_in[3];
    const float* wo = (const float*)d_in[4];
    const float* fc = (const float*)d_in[7];
    const float* fs = (const float*)d_in[8];
    float* out = (float*)d_out;
    (void)in_sizes; (void)n_in; (void)out_size;

    __half *xh, *wqkvh, *woh, *xqh, *xkh, *xvh, *aoh;
    cudaGetSymbolAddress((void**)&xh,    g_xh);
    cudaGetSymbolAddress((void**)&wqkvh, g_wqkvh);
    cudaGetSymbolAddress((void**)&woh,   g_woh);
    cudaGetSymbolAddress((void**)&xqh,   g_xqh);
    cudaGetSymbolAddress((void**)&xkh,   g_xkh);
    cudaGetSymbolAddress((void**)&xvh,   g_xvh);
    cudaGetSymbolAddress((void**)&aoh,   g_aoh);

    cudaFuncSetAttribute(gemm_qkv, cudaFuncAttributeMaxDynamicSharedMemorySize,
                         GSMEM_BYTES);
    cudaFuncSetAttribute(gemm_fp16, cudaFuncAttributeMaxDynamicSharedMemorySize,
                         GSMEM_BYTES);
    cudaFuncSetAttribute(attn_kernel, cudaFuncAttributeMaxDynamicSharedMemorySize,
                         ATT_SMEM_BYTES);

    // converts (16 elems/thread)
    to_half<<<(NTOK * DIM)  / 4096, 256>>>(x,  xh);
    to_half_slice<<<(DIM * DIM)   / 4096, 256>>>(wq, wqkvh, 12, NQKV, 0);
    to_half_slice<<<(DIM * KVDIM) / 4096, 256>>>(wk, wqkvh, 10, NQKV, DIM);
    to_half_slice<<<(DIM * KVDIM) / 4096, 256>>>(wv, wqkvh, 10, NQKV, DIM + KVDIM);
    to_half<<<(DIM * DIM) / 4096, 256>>>(wo, woh);

    // fused QKV projection + RoPE + fp16 writes (1536 CTAs @ 2/SM)
    gemm_qkv<<<dim3(NQKV / GBN, NTOK / GBM), 128, GSMEM_BYTES>>>(
        xh, wqkvh, fc, fs, xqh, xkh, xvh);

    // causal attention (fp16 in/out)
    attn_kernel<<<dim3(SEQL / 128, NH, BSZ), 256, ATT_SMEM_BYTES>>>(xqh, xkh, xvh, aoh);

    // output projection (fp32 out, 1024 CTAs @ 2/SM)
    gemm_fp16<<<dim3(DIM / GBN, NTOK / GBM), 128, GSMEM_BYTES>>>(aoh, woh, out, NTOK, DIM, DIM);
}